// round 11
// baseline (speedup 1.0000x reference)
#include <cuda_runtime.h>

#define EPS    1e-5f
#define V_DIM  32
#define D_DIM  128
#define GRID   148         // persistent: one CTA per SM (safe lower bound)

// ---------------------------------------------------------------------------
// Persistent version of the R7 winner. 1024-thread CTA = 32 warps; warp w
// owns variable v = w. Each CTA owns a CONTIGUOUS chunk of ~221 n-units
// (16KB each) and processes them in 4-unit batches (64KB dense CTA
// footprint per batch — the proven evict-first condition).
// Prologue (register tables + shuffle stats, analytic LayerNorm:
//   h = x*W + b ; mu = x*Wbar + bbar ; var = x^2 VarW + 2x Cov + Varb)
// now runs once per SM instead of ~7x.
// ---------------------------------------------------------------------------
__global__ void __launch_bounds__(1024, 1)
ve_kernel(const float* __restrict__ x,
          const float* __restrict__ W,
          const float* __restrict__ b,
          const float* __restrict__ gamma,
          const float* __restrict__ beta,
          float* __restrict__ out,
          int q, int r) {             // n_units = q*GRID + r
    int v    = threadIdx.x >> 5;     // warp id = variable index
    int lane = threadIdx.x & 31;

    int t = v * 32 + lane;           // [V, D/4] table index
    float4 w4 = __ldg(reinterpret_cast<const float4*>(W)     + t);
    float4 b4 = __ldg(reinterpret_cast<const float4*>(b)     + t);
    float4 g4 = __ldg(reinterpret_cast<const float4*>(gamma) + t);
    float4 e4 = __ldg(reinterpret_cast<const float4*>(beta)  + t);

    // ---- per-v stats via butterfly reductions ----
    float sw = w4.x + w4.y + w4.z + w4.w;
    float sb = b4.x + b4.y + b4.z + b4.w;
    #pragma unroll
    for (int off = 16; off > 0; off >>= 1) {
        sw += __shfl_xor_sync(0xFFFFFFFFu, sw, off);
        sb += __shfl_xor_sync(0xFFFFFFFFu, sb, off);
    }
    float Wbar = sw * (1.0f / D_DIM);
    float bbar = sb * (1.0f / D_DIM);

    float wc0 = w4.x - Wbar, wc1 = w4.y - Wbar, wc2 = w4.z - Wbar, wc3 = w4.w - Wbar;
    float bc0 = b4.x - bbar, bc1 = b4.y - bbar, bc2 = b4.z - bbar, bc3 = b4.w - bbar;
    float sww = wc0*wc0 + wc1*wc1 + wc2*wc2 + wc3*wc3;
    float swb = wc0*bc0 + wc1*bc1 + wc2*bc2 + wc3*bc3;
    float sbb = bc0*bc0 + bc1*bc1 + bc2*bc2 + bc3*bc3;
    #pragma unroll
    for (int off = 16; off > 0; off >>= 1) {
        sww += __shfl_xor_sync(0xFFFFFFFFu, sww, off);
        swb += __shfl_xor_sync(0xFFFFFFFFu, swb, off);
        sbb += __shfl_xor_sync(0xFFFFFFFFu, sbb, off);
    }
    float varW = sww * (1.0f / D_DIM);
    float cov2 = swb * (2.0f / D_DIM);   // 2*Cov(W,b)
    float varb = sbb * (1.0f / D_DIM);

    // ---- this CTA's contiguous chunk of n-units ----
    int bid   = blockIdx.x;
    int start = bid * q + min(bid, r);
    int cnt   = q + (bid < r ? 1 : 0);

    const float* xp = x + (size_t)start * V_DIM + v;            // x[n*V + v]
    float4* orow = reinterpret_cast<float4*>(out)
                 + ((size_t)start * V_DIM + v) * 32 + lane;     // row base
    const int UNIT4 = V_DIM * 32;                                // float4s per unit

    #define ROW_OUT(o, xv, rs, nm)                                        \
    {                                                                     \
        { float h = fmaf(w4.x, xv, b4.x); float y = fmaf(h, rs, nm);      \
          o.x = fmaxf(fmaf(g4.x, y, e4.x), 0.0f); }                       \
        { float h = fmaf(w4.y, xv, b4.y); float y = fmaf(h, rs, nm);      \
          o.y = fmaxf(fmaf(g4.y, y, e4.y), 0.0f); }                       \
        { float h = fmaf(w4.z, xv, b4.z); float y = fmaf(h, rs, nm);      \
          o.z = fmaxf(fmaf(g4.z, y, e4.z), 0.0f); }                       \
        { float h = fmaf(w4.w, xv, b4.w); float y = fmaf(h, rs, nm);      \
          o.w = fmaxf(fmaf(g4.w, y, e4.w), 0.0f); }                       \
    }

    int i = 0;
    for (; i + 3 < cnt; i += 4) {
        // front-batch 4 independent x loads
        float xv0 = __ldg(xp + (size_t)(i)     * V_DIM);
        float xv1 = __ldg(xp + (size_t)(i + 1) * V_DIM);
        float xv2 = __ldg(xp + (size_t)(i + 2) * V_DIM);
        float xv3 = __ldg(xp + (size_t)(i + 3) * V_DIM);

        float rs0 = rsqrtf(fmaf(xv0, fmaf(xv0, varW, cov2), varb) + EPS);
        float rs1 = rsqrtf(fmaf(xv1, fmaf(xv1, varW, cov2), varb) + EPS);
        float rs2 = rsqrtf(fmaf(xv2, fmaf(xv2, varW, cov2), varb) + EPS);
        float rs3 = rsqrtf(fmaf(xv3, fmaf(xv3, varW, cov2), varb) + EPS);
        float nm0 = -fmaf(xv0, Wbar, bbar) * rs0;
        float nm1 = -fmaf(xv1, Wbar, bbar) * rs1;
        float nm2 = -fmaf(xv2, Wbar, bbar) * rs2;
        float nm3 = -fmaf(xv3, Wbar, bbar) * rs3;

        float4 o0; ROW_OUT(o0, xv0, rs0, nm0);
        float4 o1; ROW_OUT(o1, xv1, rs1, nm1);
        __stcs(orow + (size_t)(i)     * UNIT4, o0);
        __stcs(orow + (size_t)(i + 1) * UNIT4, o1);
        float4 o2; ROW_OUT(o2, xv2, rs2, nm2);
        float4 o3; ROW_OUT(o3, xv3, rs3, nm3);
        __stcs(orow + (size_t)(i + 2) * UNIT4, o2);
        __stcs(orow + (size_t)(i + 3) * UNIT4, o3);
    }
    // tail: remaining 0..3 units
    for (; i < cnt; i++) {
        float xv  = __ldg(xp + (size_t)i * V_DIM);
        float rs  = rsqrtf(fmaf(xv, fmaf(xv, varW, cov2), varb) + EPS);
        float nm  = -fmaf(xv, Wbar, bbar) * rs;
        float4 o; ROW_OUT(o, xv, rs, nm);
        __stcs(orow + (size_t)i * UNIT4, o);
    }
    #undef ROW_OUT
}

// ---------------------------------------------------------------------------
extern "C" void kernel_launch(void* const* d_in, const int* in_sizes, int n_in,
                              void* d_out, int out_size) {
    const float* x     = (const float*)d_in[0];
    const float* W     = (const float*)d_in[1];
    const float* b     = (const float*)d_in[2];
    const float* gamma = (const float*)d_in[3];
    const float* beta  = (const float*)d_in[4];
    float* out = (float*)d_out;

    // n-units of 16KB = out_size / (V*D) = 32768
    int n_units = out_size / (V_DIM * D_DIM);
    int q = n_units / GRID;      // 221
    int r = n_units % GRID;      // 60

    ve_kernel<<<GRID, 1024>>>(x, W, b, gamma, beta, out, q, r);
}

// round 12
// speedup vs baseline: 1.0660x; 1.0660x over previous
#include <cuda_runtime.h>

#define EPS    1e-5f
#define V_DIM  32
#define D_DIM  128
#define NPER   16          // n-units (16KB each) per CTA, processed 4 at a time

// ---------------------------------------------------------------------------
// R7 structure with finer CTA granule (NPER 32 -> 16, grid 1024 -> 2048):
// thinner waves for better load-balance/tail absorption in the oversubscribed
// regime (persistent single-wave regressed in R11 due to CTA spread).
// 1024-thread CTA = 32 warps; warp w owns variable v = w. Each CTA iteration
// writes a CONTIGUOUS 64KB block (4 n-units) — dense CTA write footprint is
// what makes evict-first stores win (R4/R6 vs R5/R8 evidence).
// Lanes hold W/b/gamma/beta[v, lane*4..+3] in registers; warp computes per-v
// stats once via shuffles (analytic LayerNorm — no per-row reduction):
//   h = x*W + b ; mu = x*Wbar + bbar ; var = x^2 VarW + 2x Cov + Varb
// ---------------------------------------------------------------------------
__global__ void __launch_bounds__(1024, 1)
ve_kernel(const float* __restrict__ x,
          const float* __restrict__ W,
          const float* __restrict__ b,
          const float* __restrict__ gamma,
          const float* __restrict__ beta,
          float* __restrict__ out) {
    int v    = threadIdx.x >> 5;     // warp id = variable index
    int lane = threadIdx.x & 31;

    int t = v * 32 + lane;           // [V, D/4] table index
    float4 w4 = __ldg(reinterpret_cast<const float4*>(W)     + t);
    float4 b4 = __ldg(reinterpret_cast<const float4*>(b)     + t);
    float4 g4 = __ldg(reinterpret_cast<const float4*>(gamma) + t);
    float4 e4 = __ldg(reinterpret_cast<const float4*>(beta)  + t);

    // ---- per-v stats via butterfly reductions ----
    float sw = w4.x + w4.y + w4.z + w4.w;
    float sb = b4.x + b4.y + b4.z + b4.w;
    #pragma unroll
    for (int off = 16; off > 0; off >>= 1) {
        sw += __shfl_xor_sync(0xFFFFFFFFu, sw, off);
        sb += __shfl_xor_sync(0xFFFFFFFFu, sb, off);
    }
    float Wbar = sw * (1.0f / D_DIM);
    float bbar = sb * (1.0f / D_DIM);

    float wc0 = w4.x - Wbar, wc1 = w4.y - Wbar, wc2 = w4.z - Wbar, wc3 = w4.w - Wbar;
    float bc0 = b4.x - bbar, bc1 = b4.y - bbar, bc2 = b4.z - bbar, bc3 = b4.w - bbar;
    float sww = wc0*wc0 + wc1*wc1 + wc2*wc2 + wc3*wc3;
    float swb = wc0*bc0 + wc1*bc1 + wc2*bc2 + wc3*bc3;
    float sbb = bc0*bc0 + bc1*bc1 + bc2*bc2 + bc3*bc3;
    #pragma unroll
    for (int off = 16; off > 0; off >>= 1) {
        sww += __shfl_xor_sync(0xFFFFFFFFu, sww, off);
        swb += __shfl_xor_sync(0xFFFFFFFFu, swb, off);
        sbb += __shfl_xor_sync(0xFFFFFFFFu, sbb, off);
    }
    float varW = sww * (1.0f / D_DIM);
    float cov2 = swb * (2.0f / D_DIM);   // 2*Cov(W,b)
    float varb = sbb * (1.0f / D_DIM);

    int n0 = blockIdx.x * NPER;
    const float* xp = x + (size_t)n0 * V_DIM + v;               // x[n*V + v]
    float4* orow = reinterpret_cast<float4*>(out)
                 + ((size_t)n0 * V_DIM + v) * 32 + lane;        // row base
    const int UNIT4 = V_DIM * 32;                                // float4s per n-unit

    #pragma unroll 2
    for (int i = 0; i < NPER / 4; i++) {
        // front-batch 4 independent x loads
        float xv0 = __ldg(xp + (size_t)(4 * i)     * V_DIM);
        float xv1 = __ldg(xp + (size_t)(4 * i + 1) * V_DIM);
        float xv2 = __ldg(xp + (size_t)(4 * i + 2) * V_DIM);
        float xv3 = __ldg(xp + (size_t)(4 * i + 3) * V_DIM);

        float rs0 = rsqrtf(fmaf(xv0, fmaf(xv0, varW, cov2), varb) + EPS);
        float rs1 = rsqrtf(fmaf(xv1, fmaf(xv1, varW, cov2), varb) + EPS);
        float rs2 = rsqrtf(fmaf(xv2, fmaf(xv2, varW, cov2), varb) + EPS);
        float rs3 = rsqrtf(fmaf(xv3, fmaf(xv3, varW, cov2), varb) + EPS);
        float nm0 = -fmaf(xv0, Wbar, bbar) * rs0;
        float nm1 = -fmaf(xv1, Wbar, bbar) * rs1;
        float nm2 = -fmaf(xv2, Wbar, bbar) * rs2;
        float nm3 = -fmaf(xv3, Wbar, bbar) * rs3;

        #define ROW_OUT(o, xv, rs, nm)                                        \
        {                                                                     \
            { float h = fmaf(w4.x, xv, b4.x); float y = fmaf(h, rs, nm);      \
              o.x = fmaxf(fmaf(g4.x, y, e4.x), 0.0f); }                       \
            { float h = fmaf(w4.y, xv, b4.y); float y = fmaf(h, rs, nm);      \
              o.y = fmaxf(fmaf(g4.y, y, e4.y), 0.0f); }                       \
            { float h = fmaf(w4.z, xv, b4.z); float y = fmaf(h, rs, nm);      \
              o.z = fmaxf(fmaf(g4.z, y, e4.z), 0.0f); }                       \
            { float h = fmaf(w4.w, xv, b4.w); float y = fmaf(h, rs, nm);      \
              o.w = fmaxf(fmaf(g4.w, y, e4.w), 0.0f); }                       \
        }

        float4 o0; ROW_OUT(o0, xv0, rs0, nm0);
        float4 o1; ROW_OUT(o1, xv1, rs1, nm1);
        __stcs(orow + (size_t)(4 * i)     * UNIT4, o0);
        __stcs(orow + (size_t)(4 * i + 1) * UNIT4, o1);
        float4 o2; ROW_OUT(o2, xv2, rs2, nm2);
        float4 o3; ROW_OUT(o3, xv3, rs3, nm3);
        __stcs(orow + (size_t)(4 * i + 2) * UNIT4, o2);
        __stcs(orow + (size_t)(4 * i + 3) * UNIT4, o3);

        #undef ROW_OUT
    }
}

// ---------------------------------------------------------------------------
extern "C" void kernel_launch(void* const* d_in, const int* in_sizes, int n_in,
                              void* d_out, int out_size) {
    const float* x     = (const float*)d_in[0];
    const float* W     = (const float*)d_in[1];
    const float* b     = (const float*)d_in[2];
    const float* gamma = (const float*)d_in[3];
    const float* beta  = (const float*)d_in[4];
    float* out = (float*)d_out;

    // n-units of 16KB = out_size / (V*D) = 32768 ; blocks = 32768/NPER = 2048
    int n_units = out_size / (V_DIM * D_DIM);
    int blocks  = n_units / NPER;

    ve_kernel<<<blocks, 1024>>>(x, W, b, gamma, beta, out);
}